// round 7
// baseline (speedup 1.0000x reference)
#include <cuda_runtime.h>
#include <cuda_bf16.h>
#include <mma.h>
#include <cstdint>

using namespace nvcuda;

#define DI __device__ __forceinline__

static constexpr int NT = 512;
static constexpr int SB = 136;   // bf16 tile stride (elems)
static constexpr int SP = 72;    // P (alphas) bf16 stride
static constexpr int SF = 132;   // fp32 proj temp stride
static constexpr int SS = 68;    // fp32 scores temp stride

// ---- smem byte offsets ----
static constexpr int XHI = 0;        // x hi [64][SB]  (17408 B each)
static constexpr int XLO = 17408;
static constexpr int WA  = 34816;    // W buffer A [128][SB] (34816 B)
static constexpr int WB  = 69632;    // W buffer B; aliases fp32 proj TMP
static constexpr int QHI = 104448;   // q hi; later P hi [64][SP]
static constexpr int QLO = 121856;
static constexpr int KHI = 139264;   // k hi; later fp32 scores TMP [64][SS]
static constexpr int KLO = 156672;
static constexpr int VHI = 174080;
static constexpr int VLO = 191488;
static constexpr int SMEM_BYTES = 208896;   // 204 KB -> 1 CTA/SM

// prepped W^T (row = e, col = d), bf16 hi/lo
__device__ __align__(16) __nv_bfloat16 g_Whi[4][128 * 128];
__device__ __align__(16) __nv_bfloat16 g_Wlo[4][128 * 128];

DI unsigned pack2(__nv_bfloat16 a, __nv_bfloat16 b) {
    return (unsigned)__bfloat16_as_ushort(a) | ((unsigned)__bfloat16_as_ushort(b) << 16);
}
DI void split2(float v0, float v1, unsigned& h, unsigned& l) {
    __nv_bfloat16 h0 = __float2bfloat16_rn(v0), h1 = __float2bfloat16_rn(v1);
    __nv_bfloat16 l0 = __float2bfloat16_rn(v0 - __bfloat162float(h0));
    __nv_bfloat16 l1 = __float2bfloat16_rn(v1 - __bfloat162float(h1));
    h = pack2(h0, h1); l = pack2(l0, l1);
}

DI void cpa16(uint32_t dst, const void* src) {
    asm volatile("cp.async.cg.shared.global [%0], [%1], 16;" :: "r"(dst), "l"(src));
}
#define CPA_COMMIT() asm volatile("cp.async.commit_group;" ::: "memory")
#define CPA_WAIT()   asm volatile("cp.async.wait_group 0;" ::: "memory")

// ---------------------------------------------------------------- prep kernel
__global__ void prep_weights(const float* __restrict__ Wq, const float* __restrict__ Wk,
                             const float* __restrict__ Wv, const float* __restrict__ Wr) {
    const float* Ws[4] = {Wq, Wk, Wv, Wr};
    int i = blockIdx.x * 256 + threadIdx.x;          // 65536 threads
    int p = i >> 14, rem = i & 16383;
    int d = rem >> 7, e = rem & 127;
    float w = Ws[p][rem];
    __nv_bfloat16 hi = __float2bfloat16_rn(w);
    g_Whi[p][e * 128 + d] = hi;                      // transposed: [e][d]
    g_Wlo[p][e * 128 + d] = __float2bfloat16_rn(w - __bfloat162float(hi));
}

// ---------------------------------------------------------------- main kernel
using FA  = wmma::fragment<wmma::matrix_a, 16, 16, 16, __nv_bfloat16, wmma::row_major>;
using FBc = wmma::fragment<wmma::matrix_b, 16, 16, 16, __nv_bfloat16, wmma::col_major>;
using FBr = wmma::fragment<wmma::matrix_b, 16, 16, 16, __nv_bfloat16, wmma::row_major>;
using FC  = wmma::fragment<wmma::accumulator, 16, 16, 16, float>;

__global__ __launch_bounds__(NT, 1)
void autoint_hmma(const float* __restrict__ x, float* __restrict__ out) {
    extern __shared__ __align__(16) char sm[];
    const uint32_t smb = (uint32_t)__cvta_generic_to_shared(sm);
    const int b   = blockIdx.x;
    const int tid = threadIdx.x;
    const int wid = tid >> 5;

    // warp tiles: proj/epilogue 1m x 2n; scores 1m x 1n
    const int m0  = (wid >> 2) * 16;
    const int n0  = (wid & 3) * 32;
    const int sn0 = (wid & 3) * 16;

    const __nv_bfloat16* xhi = (const __nv_bfloat16*)(sm + XHI);
    const __nv_bfloat16* xlo = (const __nv_bfloat16*)(sm + XLO);
    const __nv_bfloat16* wa  = (const __nv_bfloat16*)(sm + WA);
    const __nv_bfloat16* wb  = (const __nv_bfloat16*)(sm + WB);

    // async-stage one 128x128 bf16 W matrix into smem buffer (row stride SB)
    auto stageW = [&](int dst, const __nv_bfloat16* g) {
        const char* gs = (const char*)g;
#pragma unroll
        for (int i = 0; i < 4; i++) {
            int idx = tid + i * NT;                   // 2048 x 16B chunks
            int e = idx >> 4, c = idx & 15;
            cpa16(smb + dst + e * (SB * 2) + c * 16, gs + idx * 16);
        }
        CPA_COMMIT();
    };

    // ---- phase 0: stage Wq_hi (async) while loading + splitting x ----
    stageW(WA, g_Whi[0]);
    {
        const float4* gx = (const float4*)(x + (size_t)b * 8192);
#pragma unroll
        for (int i = 0; i < 4; i++) {
            int idx = tid + i * NT;
            int row = idx >> 5, c = (idx & 31) * 4;
            float4 f = gx[idx];
            unsigned h0, l0, h1, l1;
            split2(f.x, f.y, h0, l0);
            split2(f.z, f.w, h1, l1);
            *(uint2*)(sm + XHI + (row * SB + c) * 2) = make_uint2(h0, h1);
            *(uint2*)(sm + XLO + (row * SB + c) * 2) = make_uint2(l0, l1);
        }
    }
    CPA_WAIT();
    __syncthreads();

    // ---- projections q, k, v (two passes each; W staged async one step ahead)
    const int DH[3] = {QHI, KHI, VHI};
    const int DL[3] = {QLO, KLO, VLO};
#pragma unroll 1
    for (int p = 0; p < 3; p++) {
        FC a0, a1;
        wmma::fill_fragment(a0, 0.0f);
        wmma::fill_fragment(a1, 0.0f);

        // pass1: Xhi@Whi + Xlo@Whi (WA); meanwhile stage Wp_lo -> WB
        stageW(WB, g_Wlo[p]);
#pragma unroll 1
        for (int k = 0; k < 128; k += 16) {
            FA ah, al;
            FBc b0, b1;
            wmma::load_matrix_sync(ah, xhi + m0 * SB + k, SB);
            wmma::load_matrix_sync(al, xlo + m0 * SB + k, SB);
            wmma::load_matrix_sync(b0, wa + n0 * SB + k, SB);
            wmma::load_matrix_sync(b1, wa + (n0 + 16) * SB + k, SB);
            wmma::mma_sync(a0, ah, b0, a0);
            wmma::mma_sync(a1, ah, b1, a1);
            wmma::mma_sync(a0, al, b0, a0);
            wmma::mma_sync(a1, al, b1, a1);
        }
        CPA_WAIT();
        __syncthreads();

        // pass2: Xhi@Wlo (WB); meanwhile stage W(p+1)_hi -> WA
        stageW(WA, g_Whi[p + 1]);
#pragma unroll 1
        for (int k = 0; k < 128; k += 16) {
            FA ah;
            FBc c0, c1;
            wmma::load_matrix_sync(ah, xhi + m0 * SB + k, SB);
            wmma::load_matrix_sync(c0, wb + n0 * SB + k, SB);
            wmma::load_matrix_sync(c1, wb + (n0 + 16) * SB + k, SB);
            wmma::mma_sync(a0, ah, c0, a0);
            wmma::mma_sync(a1, ah, c1, a1);
        }
        CPA_WAIT();
        __syncthreads();

        // acc -> fp32 TMP (aliases WB, now dead)
        float* tmpp = (float*)(sm + WB);
        wmma::store_matrix_sync(tmpp + m0 * SF + n0, a0, SF, wmma::mem_row_major);
        wmma::store_matrix_sync(tmpp + m0 * SF + n0 + 16, a1, SF, wmma::mem_row_major);
        __syncthreads();

        // convert TMP -> bf16 hi/lo destination
        {
            const int r = tid >> 3, c0v = (tid & 7) * 16;
#pragma unroll
            for (int j = 0; j < 4; j++) {
                float4 f = *(const float4*)(tmpp + r * SF + c0v + j * 4);
                unsigned h0, l0, h1, l1;
                split2(f.x, f.y, h0, l0);
                split2(f.z, f.w, h1, l1);
                *(uint2*)(sm + DH[p] + (r * SB + c0v + j * 4) * 2) = make_uint2(h0, h1);
                *(uint2*)(sm + DL[p] + (r * SB + c0v + j * 4) * 2) = make_uint2(l0, l1);
            }
        }
        __syncthreads();
    }
    // WA now holds Wr_hi (staged during v pass2)

    // ---- scores = Q @ K^T (64x64, K=128); stage Wr_lo -> WB meanwhile ----
    {
        stageW(WB, g_Wlo[3]);
        const __nv_bfloat16* qhi = (const __nv_bfloat16*)(sm + QHI);
        const __nv_bfloat16* qlo = (const __nv_bfloat16*)(sm + QLO);
        const __nv_bfloat16* khi = (const __nv_bfloat16*)(sm + KHI);
        const __nv_bfloat16* klo = (const __nv_bfloat16*)(sm + KLO);
        FC acc;
        wmma::fill_fragment(acc, 0.0f);
#pragma unroll 1
        for (int k = 0; k < 128; k += 16) {
            FA qh, ql;
            FBc kh, kl;
            wmma::load_matrix_sync(qh, qhi + m0 * SB + k, SB);
            wmma::load_matrix_sync(ql, qlo + m0 * SB + k, SB);
            wmma::load_matrix_sync(kh, khi + sn0 * SB + k, SB);
            wmma::load_matrix_sync(kl, klo + sn0 * SB + k, SB);
            wmma::mma_sync(acc, qh, kh, acc);
            wmma::mma_sync(acc, qh, kl, acc);
            wmma::mma_sync(acc, ql, kh, acc);
        }
        CPA_WAIT();
        __syncthreads();   // all warps done reading K before overwrite
        float* tmps = (float*)(sm + KHI);
        wmma::store_matrix_sync(tmps + m0 * SS + sn0, acc, SS, wmma::mem_row_major);
        __syncthreads();
    }

    // ---- softmax rows -> P hi/lo (overwrites Q, stride SP) ----
    {
        const float* tmps = (const float*)(sm + KHI);
        const int r = tid >> 3, g = (tid & 7) * 8;
        float s[8];
        float4 f0 = *(const float4*)(tmps + r * SS + g);
        float4 f1 = *(const float4*)(tmps + r * SS + g + 4);
        s[0] = f0.x; s[1] = f0.y; s[2] = f0.z; s[3] = f0.w;
        s[4] = f1.x; s[5] = f1.y; s[6] = f1.z; s[7] = f1.w;
        float mx = s[0];
#pragma unroll
        for (int j = 1; j < 8; j++) mx = fmaxf(mx, s[j]);
        mx = fmaxf(mx, __shfl_xor_sync(0xffffffffu, mx, 1));
        mx = fmaxf(mx, __shfl_xor_sync(0xffffffffu, mx, 2));
        mx = fmaxf(mx, __shfl_xor_sync(0xffffffffu, mx, 4));
        float sum = 0.f;
#pragma unroll
        for (int j = 0; j < 8; j++) { s[j] = __expf(s[j] - mx); sum += s[j]; }
        sum += __shfl_xor_sync(0xffffffffu, sum, 1);
        sum += __shfl_xor_sync(0xffffffffu, sum, 2);
        sum += __shfl_xor_sync(0xffffffffu, sum, 4);
        const float inv = 1.0f / sum;
#pragma unroll
        for (int j = 0; j < 8; j += 2) {
            unsigned h, l;
            split2(s[j] * inv, s[j + 1] * inv, h, l);
            *(unsigned*)(sm + QHI + (r * SP + g + j) * 2) = h;
            *(unsigned*)(sm + QLO + (r * SP + g + j) * 2) = l;
        }
    }
    __syncthreads();

    // ---- epilogue: acc = P@V + X@Wr, relu, store ----
    {
        const __nv_bfloat16* phi = (const __nv_bfloat16*)(sm + QHI);
        const __nv_bfloat16* plo = (const __nv_bfloat16*)(sm + QLO);
        const __nv_bfloat16* vhi = (const __nv_bfloat16*)(sm + VHI);
        const __nv_bfloat16* vlo = (const __nv_bfloat16*)(sm + VLO);
        FC a0, a1;
        wmma::fill_fragment(a0, 0.0f);
        wmma::fill_fragment(a1, 0.0f);

        // P @ V : K=64, B row-major
#pragma unroll 1
        for (int k = 0; k < 64; k += 16) {
            FA ph, pl;
            FBr v0h, v1h, v0l, v1l;
            wmma::load_matrix_sync(ph, phi + m0 * SP + k, SP);
            wmma::load_matrix_sync(pl, plo + m0 * SP + k, SP);
            wmma::load_matrix_sync(v0h, vhi + k * SB + n0, SB);
            wmma::load_matrix_sync(v1h, vhi + k * SB + n0 + 16, SB);
            wmma::load_matrix_sync(v0l, vlo + k * SB + n0, SB);
            wmma::load_matrix_sync(v1l, vlo + k * SB + n0 + 16, SB);
            wmma::mma_sync(a0, ph, v0h, a0);
            wmma::mma_sync(a1, ph, v1h, a1);
            wmma::mma_sync(a0, ph, v0l, a0);
            wmma::mma_sync(a1, ph, v1l, a1);
            wmma::mma_sync(a0, pl, v0h, a0);
            wmma::mma_sync(a1, pl, v1h, a1);
        }

        // += X @ Wr : K=128, Wr_hi in WA, Wr_lo in WB (col-major B)
#pragma unroll 1
        for (int k = 0; k < 128; k += 16) {
            FA ah, al;
            FBc w0h, w1h, w0l, w1l;
            wmma::load_matrix_sync(ah, xhi + m0 * SB + k, SB);
            wmma::load_matrix_sync(al, xlo + m0 * SB + k, SB);
            wmma::load_matrix_sync(w0h, wa + n0 * SB + k, SB);
            wmma::load_matrix_sync(w1h, wa + (n0 + 16) * SB + k, SB);
            wmma::load_matrix_sync(w0l, wb + n0 * SB + k, SB);
            wmma::load_matrix_sync(w1l, wb + (n0 + 16) * SB + k, SB);
            wmma::mma_sync(a0, ah, w0h, a0);
            wmma::mma_sync(a1, ah, w1h, a1);
            wmma::mma_sync(a0, ah, w0l, a0);
            wmma::mma_sync(a1, ah, w1l, a1);
            wmma::mma_sync(a0, al, w0h, a0);
            wmma::mma_sync(a1, al, w1h, a1);
        }

        float* outp = out + (size_t)b * 8192;
#pragma unroll
        for (int e = 0; e < a0.num_elements; e++) a0.x[e] = fmaxf(a0.x[e], 0.0f);
#pragma unroll
        for (int e = 0; e < a1.num_elements; e++) a1.x[e] = fmaxf(a1.x[e], 0.0f);
        wmma::store_matrix_sync(outp + m0 * 128 + n0, a0, 128, wmma::mem_row_major);
        wmma::store_matrix_sync(outp + m0 * 128 + n0 + 16, a1, 128, wmma::mem_row_major);
    }
}

extern "C" void kernel_launch(void* const* d_in, const int* in_sizes, int n_in,
                              void* d_out, int out_size) {
    const float* x  = (const float*)d_in[0];
    const float* Wq = (const float*)d_in[1];
    const float* Wk = (const float*)d_in[2];
    const float* Wv = (const float*)d_in[3];
    const float* Wr = (const float*)d_in[4];
    float* out = (float*)d_out;

    prep_weights<<<256, 256>>>(Wq, Wk, Wv, Wr);
    cudaFuncSetAttribute(autoint_hmma,
                         cudaFuncAttributeMaxDynamicSharedMemorySize, SMEM_BYTES);
    autoint_hmma<<<8192, NT, SMEM_BYTES>>>(x, out);
}

// round 8
// speedup vs baseline: 1.1374x; 1.1374x over previous
#include <cuda_runtime.h>
#include <cuda_bf16.h>
#include <mma.h>
#include <cstdint>

using namespace nvcuda;

#define DI __device__ __forceinline__

static constexpr int NT = 256;
static constexpr int SB = 136;   // bf16 tile stride (elems)
static constexpr int SP = 72;    // P (alphas) bf16 stride
static constexpr int SF = 132;   // fp32 proj temp stride
static constexpr int SS = 68;    // fp32 scores temp stride

// ---- smem byte offsets ----
static constexpr int XHI = 0;        // x hi [64][SB]  (17408 B each)
static constexpr int XLO = 17408;
static constexpr int WA  = 34816;    // W buffer A [128][SB] (34816 B)
static constexpr int WB  = 69632;    // W buffer B; aliases fp32 proj TMP
static constexpr int QHI = 104448;   // q hi; later P hi [64][SP]
static constexpr int QLO = 121856;
static constexpr int KHI = 139264;   // k hi; later fp32 scores TMP [64][SS]
static constexpr int KLO = 156672;
static constexpr int VHI = 174080;
static constexpr int VLO = 191488;
static constexpr int SMEM_BYTES = 208896;   // 204 KB -> 1 CTA/SM

// prepped W^T (row = e, col = d), bf16 hi/lo
__device__ __align__(16) __nv_bfloat16 g_Whi[4][128 * 128];
__device__ __align__(16) __nv_bfloat16 g_Wlo[4][128 * 128];

DI unsigned pack2(__nv_bfloat16 a, __nv_bfloat16 b) {
    return (unsigned)__bfloat16_as_ushort(a) | ((unsigned)__bfloat16_as_ushort(b) << 16);
}
DI void split2(float v0, float v1, unsigned& h, unsigned& l) {
    __nv_bfloat16 h0 = __float2bfloat16_rn(v0), h1 = __float2bfloat16_rn(v1);
    __nv_bfloat16 l0 = __float2bfloat16_rn(v0 - __bfloat162float(h0));
    __nv_bfloat16 l1 = __float2bfloat16_rn(v1 - __bfloat162float(h1));
    h = pack2(h0, h1); l = pack2(l0, l1);
}
DI void cpa16(uint32_t dst, const void* src) {
    asm volatile("cp.async.cg.shared.global [%0], [%1], 16;" :: "r"(dst), "l"(src));
}
#define CPA_COMMIT() asm volatile("cp.async.commit_group;" ::: "memory")
#define CPA_WAIT()   asm volatile("cp.async.wait_group 0;" ::: "memory")

// ---------------------------------------------------------------- prep kernel
__global__ void prep_weights(const float* __restrict__ Wq, const float* __restrict__ Wk,
                             const float* __restrict__ Wv, const float* __restrict__ Wr) {
    const float* Ws[4] = {Wq, Wk, Wv, Wr};
    int i = blockIdx.x * 256 + threadIdx.x;          // 65536 threads
    int p = i >> 14, rem = i & 16383;
    int d = rem >> 7, e = rem & 127;
    float w = Ws[p][rem];
    __nv_bfloat16 hi = __float2bfloat16_rn(w);
    g_Whi[p][e * 128 + d] = hi;                      // transposed: [e][d]
    g_Wlo[p][e * 128 + d] = __float2bfloat16_rn(w - __bfloat162float(hi));
}

// ---------------------------------------------------------------- main kernel
using FA  = wmma::fragment<wmma::matrix_a, 16, 16, 16, __nv_bfloat16, wmma::row_major>;
using FBc = wmma::fragment<wmma::matrix_b, 16, 16, 16, __nv_bfloat16, wmma::col_major>;
using FBr = wmma::fragment<wmma::matrix_b, 16, 16, 16, __nv_bfloat16, wmma::row_major>;
using FC  = wmma::fragment<wmma::accumulator, 16, 16, 16, float>;

__global__ __launch_bounds__(NT, 1)
void autoint_hmma(const float* __restrict__ x, float* __restrict__ out) {
    extern __shared__ __align__(16) char sm[];
    const uint32_t smb = (uint32_t)__cvta_generic_to_shared(sm);
    const int b   = blockIdx.x;
    const int tid = threadIdx.x;
    const int wid = tid >> 5;

    // warp tiles (round-6 geometry): proj/epilogue 2m x 2n
    const int m0  = 32 * (wid >> 2);
    const int n0  = 32 * (wid & 3);

    const __nv_bfloat16* xhi = (const __nv_bfloat16*)(sm + XHI);
    const __nv_bfloat16* xlo = (const __nv_bfloat16*)(sm + XLO);
    const __nv_bfloat16* wa  = (const __nv_bfloat16*)(sm + WA);
    const __nv_bfloat16* wb  = (const __nv_bfloat16*)(sm + WB);

    // async-stage one 128x128 bf16 W matrix (row stride SB)
    auto stageW = [&](int dst, const __nv_bfloat16* g) {
        const char* gs = (const char*)g;
#pragma unroll
        for (int i = 0; i < 8; i++) {
            int idx = tid + i * NT;                   // 2048 x 16B chunks
            int e = idx >> 4, c = idx & 15;
            cpa16(smb + dst + e * (SB * 2) + c * 16, gs + idx * 16);
        }
        CPA_COMMIT();
    };

    // ---- phase 0: async-stage Wq_hi while loading + splitting x ----
    stageW(WA, g_Whi[0]);
    {
        const float4* gx = (const float4*)(x + (size_t)b * 8192);
#pragma unroll
        for (int i = 0; i < 8; i++) {
            int idx = tid + i * NT;
            int row = idx >> 5, c = (idx & 31) * 4;
            float4 f = gx[idx];
            unsigned h0, l0, h1, l1;
            split2(f.x, f.y, h0, l0);
            split2(f.z, f.w, h1, l1);
            *(uint2*)(sm + XHI + (row * SB + c) * 2) = make_uint2(h0, h1);
            *(uint2*)(sm + XLO + (row * SB + c) * 2) = make_uint2(l0, l1);
        }
    }
    CPA_WAIT();
    __syncthreads();

    // ---- projections q, k, v (2 passes; next W staged async during MMAs) ----
    const int DH[3] = {QHI, KHI, VHI};
    const int DL[3] = {QLO, KLO, VLO};
#pragma unroll 1
    for (int p = 0; p < 3; p++) {
        FC acc[2][2];
#pragma unroll
        for (int i = 0; i < 2; i++)
#pragma unroll
            for (int j = 0; j < 2; j++) wmma::fill_fragment(acc[i][j], 0.0f);

        // pass1: (Xhi + Xlo) @ Whi  (reads WA); stage Wlo[p] -> WB meanwhile
        stageW(WB, g_Wlo[p]);
#pragma unroll 1
        for (int k = 0; k < 128; k += 16) {
            FA ah[2], al[2];
            FBc bh[2];
#pragma unroll
            for (int i = 0; i < 2; i++) {
                wmma::load_matrix_sync(ah[i], xhi + (m0 + 16 * i) * SB + k, SB);
                wmma::load_matrix_sync(al[i], xlo + (m0 + 16 * i) * SB + k, SB);
            }
#pragma unroll
            for (int j = 0; j < 2; j++)
                wmma::load_matrix_sync(bh[j], wa + (n0 + 16 * j) * SB + k, SB);
#pragma unroll
            for (int i = 0; i < 2; i++)
#pragma unroll
                for (int j = 0; j < 2; j++) {
                    wmma::mma_sync(acc[i][j], ah[i], bh[j], acc[i][j]);
                    wmma::mma_sync(acc[i][j], al[i], bh[j], acc[i][j]);
                }
        }
        CPA_WAIT();
        __syncthreads();

        // pass2: Xhi @ Wlo (reads WB); stage Whi[p+1] -> WA meanwhile
        stageW(WA, g_Whi[p + 1]);
#pragma unroll 1
        for (int k = 0; k < 128; k += 16) {
            FA ah[2];
            FBc bl[2];
#pragma unroll
            for (int i = 0; i < 2; i++)
                wmma::load_matrix_sync(ah[i], xhi + (m0 + 16 * i) * SB + k, SB);
#pragma unroll
            for (int j = 0; j < 2; j++)
                wmma::load_matrix_sync(bl[j], wb + (n0 + 16 * j) * SB + k, SB);
#pragma unroll
            for (int i = 0; i < 2; i++)
#pragma unroll
                for (int j = 0; j < 2; j++)
                    wmma::mma_sync(acc[i][j], ah[i], bl[j], acc[i][j]);
        }
        __syncthreads();   // all warps done reading WB before TMP overwrite

        // acc -> fp32 TMP (aliases WB, now dead)
        float* tmpp = (float*)(sm + WB);
#pragma unroll
        for (int i = 0; i < 2; i++)
#pragma unroll
            for (int j = 0; j < 2; j++)
                wmma::store_matrix_sync(tmpp + (m0 + 16 * i) * SF + (n0 + 16 * j),
                                        acc[i][j], SF, wmma::mem_row_major);
        __syncthreads();

        // convert TMP -> bf16 hi/lo destination
        {
            const int r = tid >> 2, c0v = (tid & 3) * 32;
#pragma unroll
            for (int jj = 0; jj < 8; jj++) {
                float4 f = *(const float4*)(tmpp + r * SF + c0v + jj * 4);
                unsigned h0, l0, h1, l1;
                split2(f.x, f.y, h0, l0);
                split2(f.z, f.w, h1, l1);
                *(uint2*)(sm + DH[p] + (r * SB + c0v + jj * 4) * 2) = make_uint2(h0, h1);
                *(uint2*)(sm + DL[p] + (r * SB + c0v + jj * 4) * 2) = make_uint2(l0, l1);
            }
        }
        __syncthreads();
    }
    // WA holds Wr_hi (staged during v pass2)

    // ---- scores = Q @ K^T (64x64, K=128); stage Wr_lo -> WB meanwhile ----
    {
        stageW(WB, g_Wlo[3]);
        const int sm0 = 16 * (wid & 3);          // 1 m-tile
        const int sn0 = 32 * (wid >> 2);         // 2 n-tiles
        const __nv_bfloat16* qhi = (const __nv_bfloat16*)(sm + QHI);
        const __nv_bfloat16* qlo = (const __nv_bfloat16*)(sm + QLO);
        const __nv_bfloat16* khi = (const __nv_bfloat16*)(sm + KHI);
        const __nv_bfloat16* klo = (const __nv_bfloat16*)(sm + KLO);
        FC acc[2];
        wmma::fill_fragment(acc[0], 0.0f);
        wmma::fill_fragment(acc[1], 0.0f);
#pragma unroll 1
        for (int k = 0; k < 128; k += 16) {
            FA qh, ql;
            FBc kh[2], kl[2];
            wmma::load_matrix_sync(qh, qhi + sm0 * SB + k, SB);
            wmma::load_matrix_sync(ql, qlo + sm0 * SB + k, SB);
#pragma unroll
            for (int j = 0; j < 2; j++) {
                wmma::load_matrix_sync(kh[j], khi + (sn0 + 16 * j) * SB + k, SB);
                wmma::load_matrix_sync(kl[j], klo + (sn0 + 16 * j) * SB + k, SB);
            }
#pragma unroll
            for (int j = 0; j < 2; j++) {
                wmma::mma_sync(acc[j], qh, kh[j], acc[j]);
                wmma::mma_sync(acc[j], qh, kl[j], acc[j]);
                wmma::mma_sync(acc[j], ql, kh[j], acc[j]);
            }
        }
        CPA_WAIT();
        __syncthreads();   // everyone done with K reads (tmp overwrites K_hi)
        float* tmps = (float*)(sm + KHI);
#pragma unroll
        for (int j = 0; j < 2; j++)
            wmma::store_matrix_sync(tmps + sm0 * SS + sn0 + 16 * j, acc[j], SS,
                                    wmma::mem_row_major);
        __syncthreads();
    }

    // ---- softmax rows -> P hi/lo (overwrites Q, stride SP) ----
    {
        const float* tmps = (const float*)(sm + KHI);
        const int r = tid >> 2, q0 = (tid & 3) * 16;
        float s[16];
#pragma unroll
        for (int j = 0; j < 16; j += 4) {
            float4 f = *(const float4*)(tmps + r * SS + q0 + j);
            s[j] = f.x; s[j + 1] = f.y; s[j + 2] = f.z; s[j + 3] = f.w;
        }
        float mx = s[0];
#pragma unroll
        for (int j = 1; j < 16; j++) mx = fmaxf(mx, s[j]);
        mx = fmaxf(mx, __shfl_xor_sync(0xffffffffu, mx, 1));
        mx = fmaxf(mx, __shfl_xor_sync(0xffffffffu, mx, 2));
        float sum = 0.f;
#pragma unroll
        for (int j = 0; j < 16; j++) { s[j] = __expf(s[j] - mx); sum += s[j]; }
        sum += __shfl_xor_sync(0xffffffffu, sum, 1);
        sum += __shfl_xor_sync(0xffffffffu, sum, 2);
        const float inv = 1.0f / sum;
#pragma unroll
        for (int j = 0; j < 16; j += 2) {
            unsigned h, l;
            split2(s[j] * inv, s[j + 1] * inv, h, l);
            *(unsigned*)(sm + QHI + (r * SP + q0 + j) * 2) = h;
            *(unsigned*)(sm + QLO + (r * SP + q0 + j) * 2) = l;
        }
    }
    __syncthreads();

    // ---- epilogue: acc = P@V + X@Wr, relu, store ----
    {
        const __nv_bfloat16* phi = (const __nv_bfloat16*)(sm + QHI);
        const __nv_bfloat16* plo = (const __nv_bfloat16*)(sm + QLO);
        const __nv_bfloat16* vhi = (const __nv_bfloat16*)(sm + VHI);
        const __nv_bfloat16* vlo = (const __nv_bfloat16*)(sm + VLO);
        FC acc[2][2];
#pragma unroll
        for (int i = 0; i < 2; i++)
#pragma unroll
            for (int j = 0; j < 2; j++) wmma::fill_fragment(acc[i][j], 0.0f);

        // P @ V : K=64, B row-major
#pragma unroll 1
        for (int k = 0; k < 64; k += 16) {
            FA ph[2], pl[2];
            FBr vh[2], vl[2];
#pragma unroll
            for (int i = 0; i < 2; i++) {
                wmma::load_matrix_sync(ph[i], phi + (m0 + 16 * i) * SP + k, SP);
                wmma::load_matrix_sync(pl[i], plo + (m0 + 16 * i) * SP + k, SP);
            }
#pragma unroll
            for (int j = 0; j < 2; j++) {
                wmma::load_matrix_sync(vh[j], vhi + k * SB + n0 + 16 * j, SB);
                wmma::load_matrix_sync(vl[j], vlo + k * SB + n0 + 16 * j, SB);
            }
#pragma unroll
            for (int i = 0; i < 2; i++)
#pragma unroll
                for (int j = 0; j < 2; j++) {
                    wmma::mma_sync(acc[i][j], ph[i], vh[j], acc[i][j]);
                    wmma::mma_sync(acc[i][j], ph[i], vl[j], acc[i][j]);
                    wmma::mma_sync(acc[i][j], pl[i], vh[j], acc[i][j]);
                }
        }

        // += X @ Wr : K=128, Wr_hi in WA, Wr_lo in WB (col-major B)
#pragma unroll 1
        for (int k = 0; k < 128; k += 16) {
            FA ah[2], al[2];
            FBc wh[2], wl[2];
#pragma unroll
            for (int i = 0; i < 2; i++) {
                wmma::load_matrix_sync(ah[i], xhi + (m0 + 16 * i) * SB + k, SB);
                wmma::load_matrix_sync(al[i], xlo + (m0 + 16 * i) * SB + k, SB);
            }
#pragma unroll
            for (int j = 0; j < 2; j++) {
                wmma::load_matrix_sync(wh[j], wa + (n0 + 16 * j) * SB + k, SB);
                wmma::load_matrix_sync(wl[j], wb + (n0 + 16 * j) * SB + k, SB);
            }
#pragma unroll
            for (int i = 0; i < 2; i++)
#pragma unroll
                for (int j = 0; j < 2; j++) {
                    wmma::mma_sync(acc[i][j], ah[i], wh[j], acc[i][j]);
                    wmma::mma_sync(acc[i][j], ah[i], wl[j], acc[i][j]);
                    wmma::mma_sync(acc[i][j], al[i], wh[j], acc[i][j]);
                }
        }

        float* outp = out + (size_t)b * 8192;
#pragma unroll
        for (int i = 0; i < 2; i++)
#pragma unroll
            for (int j = 0; j < 2; j++) {
#pragma unroll
                for (int e = 0; e < acc[i][j].num_elements; e++)
                    acc[i][j].x[e] = fmaxf(acc[i][j].x[e], 0.0f);
                wmma::store_matrix_sync(outp + (m0 + 16 * i) * 128 + (n0 + 16 * j),
                                        acc[i][j], 128, wmma::mem_row_major);
            }
    }
}

extern "C" void kernel_launch(void* const* d_in, const int* in_sizes, int n_in,
                              void* d_out, int out_size) {
    const float* x  = (const float*)d_in[0];
    const float* Wq = (const float*)d_in[1];
    const float* Wk = (const float*)d_in[2];
    const float* Wv = (const float*)d_in[3];
    const float* Wr = (const float*)d_in[4];
    float* out = (float*)d_out;

    prep_weights<<<256, 256>>>(Wq, Wk, Wv, Wr);
    cudaFuncSetAttribute(autoint_hmma,
                         cudaFuncAttributeMaxDynamicSharedMemorySize, SMEM_BYTES);
    autoint_hmma<<<8192, NT, SMEM_BYTES>>>(x, out);
}

// round 9
// speedup vs baseline: 1.4489x; 1.2738x over previous
#include <cuda_runtime.h>
#include <cuda_bf16.h>
#include <mma.h>
#include <cstdint>

using namespace nvcuda;

#define DI __device__ __forceinline__

static constexpr int NT = 256;
static constexpr int SB = 136;   // bf16 tile stride (elems)
static constexpr int SP = 72;    // P (alphas) bf16 stride
static constexpr int SF = 132;   // fp32 proj temp stride
static constexpr int SS = 68;    // fp32 scores temp stride

// ---- smem byte offsets ----
static constexpr int XHI = 0;         // x hi [64][SB]   17408 B
static constexpr int XLO = 17408;
static constexpr int WA  = 34816;     // staged W hi [128][SB]  34816 B
static constexpr int WB  = 69632;     // staged W lo
static constexpr int THI = 104448;    // T hi [64][SB]; later P [64][SP]
static constexpr int TLO = 121856;
static constexpr int VHI = 139264;    // v hi [64][SB]
static constexpr int VLO = 156672;
static constexpr int TMP = 174080;    // fp32 [64][SF] proj tmp; scores tmp aliases (stride SS)
static constexpr int SMEM_BYTES = TMP + 64 * SF * 4;   // 207872 -> 1 CTA/SM

// prepped matrices, bf16 hi/lo: slot0 = G^T (G = Wq·Wk^T), slot1 = Wv^T, slot2 = Wr^T
__device__ __align__(16) __nv_bfloat16 g_Whi[3][128 * 128];
__device__ __align__(16) __nv_bfloat16 g_Wlo[3][128 * 128];

DI unsigned pack2(__nv_bfloat16 a, __nv_bfloat16 b) {
    return (unsigned)__bfloat16_as_ushort(a) | ((unsigned)__bfloat16_as_ushort(b) << 16);
}
DI void split2(float v0, float v1, unsigned& h, unsigned& l) {
    __nv_bfloat16 h0 = __float2bfloat16_rn(v0), h1 = __float2bfloat16_rn(v1);
    __nv_bfloat16 l0 = __float2bfloat16_rn(v0 - __bfloat162float(h0));
    __nv_bfloat16 l1 = __float2bfloat16_rn(v1 - __bfloat162float(h1));
    h = pack2(h0, h1); l = pack2(l0, l1);
}
DI void cpa16(uint32_t dst, const void* src) {
    asm volatile("cp.async.cg.shared.global [%0], [%1], 16;" :: "r"(dst), "l"(src));
}
#define CPA_COMMIT() asm volatile("cp.async.commit_group;" ::: "memory")
#define CPA_WAIT()   asm volatile("cp.async.wait_group 0;" ::: "memory")

// ------------------------------------------------ prep kernels (once/replay)
// G^T[j][d] = sum_e Wq[d,e] * Wk[j,e]  (so B col-major fragment gives X@G)
__global__ void prep_g(const float* __restrict__ Wq, const float* __restrict__ Wk) {
    int idx = blockIdx.x * 256 + threadIdx.x;   // 16384
    int j = idx >> 7, d = idx & 127;
    const float* wq = Wq + d * 128;
    const float* wk = Wk + j * 128;
    float s = 0.f;
#pragma unroll 8
    for (int e = 0; e < 128; e++) s = fmaf(wq[e], wk[e], s);
    __nv_bfloat16 hi = __float2bfloat16_rn(s);
    g_Whi[0][j * 128 + d] = hi;
    g_Wlo[0][j * 128 + d] = __float2bfloat16_rn(s - __bfloat162float(hi));
}
// transpose + split Wv, Wr into slots 1, 2
__global__ void prep_w(const float* __restrict__ Wv, const float* __restrict__ Wr) {
    int i = blockIdx.x * 256 + threadIdx.x;     // 32768
    int p = i >> 14, rem = i & 16383;
    int d = rem >> 7, e = rem & 127;
    float w = (p ? Wr : Wv)[rem];
    __nv_bfloat16 hi = __float2bfloat16_rn(w);
    g_Whi[p + 1][e * 128 + d] = hi;
    g_Wlo[p + 1][e * 128 + d] = __float2bfloat16_rn(w - __bfloat162float(hi));
}

// ---------------------------------------------------------------- main kernel
using FA  = wmma::fragment<wmma::matrix_a, 16, 16, 16, __nv_bfloat16, wmma::row_major>;
using FBc = wmma::fragment<wmma::matrix_b, 16, 16, 16, __nv_bfloat16, wmma::col_major>;
using FBr = wmma::fragment<wmma::matrix_b, 16, 16, 16, __nv_bfloat16, wmma::row_major>;
using FC  = wmma::fragment<wmma::accumulator, 16, 16, 16, float>;

__global__ __launch_bounds__(NT, 1)
void autoint_hmma(const float* __restrict__ x, float* __restrict__ out) {
    extern __shared__ __align__(16) char sm[];
    const uint32_t smb = (uint32_t)__cvta_generic_to_shared(sm);
    const int b   = blockIdx.x;
    const int tid = threadIdx.x;
    const int wid = tid >> 5;

    // warp tiles: GEMMs over [64 x 128]: 2m x 2n of 16x16 per warp
    const int m0 = 32 * (wid >> 2);
    const int n0 = 32 * (wid & 3);

    const __nv_bfloat16* xhi = (const __nv_bfloat16*)(sm + XHI);
    const __nv_bfloat16* xlo = (const __nv_bfloat16*)(sm + XLO);
    const __nv_bfloat16* wa  = (const __nv_bfloat16*)(sm + WA);
    const __nv_bfloat16* wb  = (const __nv_bfloat16*)(sm + WB);
    float* tmpp = (float*)(sm + TMP);

    // async-stage one 128x128 bf16 matrix (row stride SB)
    auto stageW = [&](int dst, const __nv_bfloat16* g) {
        const char* gs = (const char*)g;
#pragma unroll
        for (int i = 0; i < 8; i++) {
            int idx = tid + i * NT;                  // 2048 x 16B chunks
            cpa16(smb + dst + (idx >> 4) * (SB * 2) + (idx & 15) * 16, gs + idx * 16);
        }
        CPA_COMMIT();
    };
    // convert fp32 TMP (stride SF) -> bf16 hi/lo tile (stride SB)
    auto convert = [&](int dh, int dl) {
        const int r = tid >> 2, c0v = (tid & 3) * 32;
#pragma unroll
        for (int jj = 0; jj < 8; jj++) {
            float4 f = *(const float4*)(tmpp + r * SF + c0v + jj * 4);
            unsigned h0, l0, h1, l1;
            split2(f.x, f.y, h0, l0);
            split2(f.z, f.w, h1, l1);
            *(uint2*)(sm + dh + (r * SB + c0v + jj * 4) * 2) = make_uint2(h0, h1);
            *(uint2*)(sm + dl + (r * SB + c0v + jj * 4) * 2) = make_uint2(l0, l1);
        }
    };

    // ---- phase 0: stage G (hi+lo, async) while loading + splitting x ----
    stageW(WA, g_Whi[0]);
    stageW(WB, g_Wlo[0]);
    {
        const float4* gx = (const float4*)(x + (size_t)b * 8192);
#pragma unroll
        for (int i = 0; i < 8; i++) {
            int idx = tid + i * NT;
            int row = idx >> 5, c = (idx & 31) * 4;
            float4 f = gx[idx];
            unsigned h0, l0, h1, l1;
            split2(f.x, f.y, h0, l0);
            split2(f.z, f.w, h1, l1);
            *(uint2*)(sm + XHI + (row * SB + c) * 2) = make_uint2(h0, h1);
            *(uint2*)(sm + XLO + (row * SB + c) * 2) = make_uint2(l0, l1);
        }
    }
    CPA_WAIT();
    __syncthreads();

    // ---- phase 1+2: T = X@G, then V = X@Wv (3-term, next W staged in convert window)
    const int DH[2] = {THI, VHI};
    const int DL[2] = {TLO, VLO};
#pragma unroll 1
    for (int p = 0; p < 2; p++) {
        FC acc[2][2];
#pragma unroll
        for (int i = 0; i < 2; i++)
#pragma unroll
            for (int j = 0; j < 2; j++) wmma::fill_fragment(acc[i][j], 0.0f);

#pragma unroll
        for (int k = 0; k < 128; k += 16) {
            FA ah[2], al[2];
            FBc bh[2], bl[2];
#pragma unroll
            for (int i = 0; i < 2; i++) {
                wmma::load_matrix_sync(ah[i], xhi + (m0 + 16 * i) * SB + k, SB);
                wmma::load_matrix_sync(al[i], xlo + (m0 + 16 * i) * SB + k, SB);
            }
#pragma unroll
            for (int j = 0; j < 2; j++) {
                wmma::load_matrix_sync(bh[j], wa + (n0 + 16 * j) * SB + k, SB);
                wmma::load_matrix_sync(bl[j], wb + (n0 + 16 * j) * SB + k, SB);
            }
#pragma unroll
            for (int i = 0; i < 2; i++)
#pragma unroll
                for (int j = 0; j < 2; j++) {
                    wmma::mma_sync(acc[i][j], ah[i], bh[j], acc[i][j]);
                    wmma::mma_sync(acc[i][j], ah[i], bl[j], acc[i][j]);
                    wmma::mma_sync(acc[i][j], al[i], bh[j], acc[i][j]);
                }
        }
        __syncthreads();                    // WA/WB reads done; TMP free

        stageW(WA, g_Whi[p + 1]);           // async: next matrix (Wv, then Wr)
        stageW(WB, g_Wlo[p + 1]);

#pragma unroll
        for (int i = 0; i < 2; i++)
#pragma unroll
            for (int j = 0; j < 2; j++)
                wmma::store_matrix_sync(tmpp + (m0 + 16 * i) * SF + (n0 + 16 * j),
                                        acc[i][j], SF, wmma::mem_row_major);
        __syncthreads();

        convert(DH[p], DL[p]);
        CPA_WAIT();
        __syncthreads();
    }
    // WA/WB now hold Wr hi/lo

    // ---- phase 3: scores = T @ X^T (64x64, K=128; B = X col-major, no staging)
    {
        const int sm0 = 16 * (wid & 3);
        const int sn0 = 32 * (wid >> 2);
        const __nv_bfloat16* thi = (const __nv_bfloat16*)(sm + THI);
        const __nv_bfloat16* tlo = (const __nv_bfloat16*)(sm + TLO);
        FC acc[2];
        wmma::fill_fragment(acc[0], 0.0f);
        wmma::fill_fragment(acc[1], 0.0f);
#pragma unroll
        for (int k = 0; k < 128; k += 16) {
            FA th, tl;
            FBc xh[2], xl[2];
            wmma::load_matrix_sync(th, thi + sm0 * SB + k, SB);
            wmma::load_matrix_sync(tl, tlo + sm0 * SB + k, SB);
#pragma unroll
            for (int j = 0; j < 2; j++) {
                wmma::load_matrix_sync(xh[j], xhi + (sn0 + 16 * j) * SB + k, SB);
                wmma::load_matrix_sync(xl[j], xlo + (sn0 + 16 * j) * SB + k, SB);
            }
#pragma unroll
            for (int j = 0; j < 2; j++) {
                wmma::mma_sync(acc[j], th, xh[j], acc[j]);
                wmma::mma_sync(acc[j], th, xl[j], acc[j]);
                wmma::mma_sync(acc[j], tl, xh[j], acc[j]);
            }
        }
        float* tmps = (float*)(sm + TMP);    // stride SS (fits in TMP region)
#pragma unroll
        for (int j = 0; j < 2; j++)
            wmma::store_matrix_sync(tmps + sm0 * SS + sn0 + 16 * j, acc[j], SS,
                                    wmma::mem_row_major);
        __syncthreads();                     // scores visible; T reads done
    }

    // ---- phase 4: softmax rows -> P hi/lo (overwrites T, stride SP) ----
    {
        const float* tmps = (const float*)(sm + TMP);
        const int r = tid >> 2, q0 = (tid & 3) * 16;
        float s[16];
#pragma unroll
        for (int j = 0; j < 16; j += 4) {
            float4 f = *(const float4*)(tmps + r * SS + q0 + j);
            s[j] = f.x; s[j + 1] = f.y; s[j + 2] = f.z; s[j + 3] = f.w;
        }
        float mx = s[0];
#pragma unroll
        for (int j = 1; j < 16; j++) mx = fmaxf(mx, s[j]);
        mx = fmaxf(mx, __shfl_xor_sync(0xffffffffu, mx, 1));
        mx = fmaxf(mx, __shfl_xor_sync(0xffffffffu, mx, 2));
        float sum = 0.f;
#pragma unroll
        for (int j = 0; j < 16; j++) { s[j] = __expf(s[j] - mx); sum += s[j]; }
        sum += __shfl_xor_sync(0xffffffffu, sum, 1);
        sum += __shfl_xor_sync(0xffffffffu, sum, 2);
        const float inv = 1.0f / sum;
#pragma unroll
        for (int j = 0; j < 16; j += 2) {
            unsigned h, l;
            split2(s[j] * inv, s[j + 1] * inv, h, l);
            *(unsigned*)(sm + THI + (r * SP + q0 + j) * 2) = h;
            *(unsigned*)(sm + TLO + (r * SP + q0 + j) * 2) = l;
        }
    }
    __syncthreads();

    // ---- phase 5: epilogue acc = P@V + X@Wr, relu, store ----
    {
        const __nv_bfloat16* phi = (const __nv_bfloat16*)(sm + THI);
        const __nv_bfloat16* plo = (const __nv_bfloat16*)(sm + TLO);
        const __nv_bfloat16* vhi = (const __nv_bfloat16*)(sm + VHI);
        const __nv_bfloat16* vlo = (const __nv_bfloat16*)(sm + VLO);
        FC acc[2][2];
#pragma unroll
        for (int i = 0; i < 2; i++)
#pragma unroll
            for (int j = 0; j < 2; j++) wmma::fill_fragment(acc[i][j], 0.0f);

        // P @ V : K=64, B row-major
#pragma unroll
        for (int k = 0; k < 64; k += 16) {
            FA ph[2], pl[2];
            FBr vh[2], vl[2];
#pragma unroll
            for (int i = 0; i < 2; i++) {
                wmma::load_matrix_sync(ph[i], phi + (m0 + 16 * i) * SP + k, SP);
                wmma::load_matrix_sync(pl[i], plo + (m0 + 16 * i) * SP + k, SP);
            }
#pragma unroll
            for (int j = 0; j < 2; j++) {
                wmma::load_matrix_sync(vh[j], vhi + k * SB + n0 + 16 * j, SB);
                wmma::load_matrix_sync(vl[j], vlo + k * SB + n0 + 16 * j, SB);
            }
#pragma unroll
            for (int i = 0; i < 2; i++)
#pragma unroll
                for (int j = 0; j < 2; j++) {
                    wmma::mma_sync(acc[i][j], ph[i], vh[j], acc[i][j]);
                    wmma::mma_sync(acc[i][j], ph[i], vl[j], acc[i][j]);
                    wmma::mma_sync(acc[i][j], pl[i], vh[j], acc[i][j]);
                }
        }

        // += X @ Wr : K=128, Wr hi/lo in WA/WB (col-major B)
#pragma unroll
        for (int k = 0; k < 128; k += 16) {
            FA ah[2], al[2];
            FBc wh[2], wl[2];
#pragma unroll
            for (int i = 0; i < 2; i++) {
                wmma::load_matrix_sync(ah[i], xhi + (m0 + 16 * i) * SB + k, SB);
                wmma::load_matrix_sync(al[i], xlo + (m0 + 16 * i) * SB + k, SB);
            }
#pragma unroll
            for (int j = 0; j < 2; j++) {
                wmma::load_matrix_sync(wh[j], wa + (n0 + 16 * j) * SB + k, SB);
                wmma::load_matrix_sync(wl[j], wb + (n0 + 16 * j) * SB + k, SB);
            }
#pragma unroll
            for (int i = 0; i < 2; i++)
#pragma unroll
                for (int j = 0; j < 2; j++) {
                    wmma::mma_sync(acc[i][j], ah[i], wh[j], acc[i][j]);
                    wmma::mma_sync(acc[i][j], ah[i], wl[j], acc[i][j]);
                    wmma::mma_sync(acc[i][j], al[i], wh[j], acc[i][j]);
                }
        }

        float* outp = out + (size_t)b * 8192;
#pragma unroll
        for (int i = 0; i < 2; i++)
#pragma unroll
            for (int j = 0; j < 2; j++) {
#pragma unroll
                for (int e = 0; e < acc[i][j].num_elements; e++)
                    acc[i][j].x[e] = fmaxf(acc[i][j].x[e], 0.0f);
                wmma::store_matrix_sync(outp + (m0 + 16 * i) * 128 + (n0 + 16 * j),
                                        acc[i][j], 128, wmma::mem_row_major);
            }
    }
}

extern "C" void kernel_launch(void* const* d_in, const int* in_sizes, int n_in,
                              void* d_out, int out_size) {
    const float* x  = (const float*)d_in[0];
    const float* Wq = (const float*)d_in[1];
    const float* Wk = (const float*)d_in[2];
    const float* Wv = (const float*)d_in[3];
    const float* Wr = (const float*)d_in[4];
    float* out = (float*)d_out;

    prep_g<<<64, 256>>>(Wq, Wk);
    prep_w<<<128, 256>>>(Wv, Wr);
    cudaFuncSetAttribute(autoint_hmma,
                         cudaFuncAttributeMaxDynamicSharedMemorySize, SMEM_BYTES);
    autoint_hmma<<<8192, NT, SMEM_BYTES>>>(x, out);
}